// round 1
// baseline (speedup 1.0000x reference)
#include <cuda_runtime.h>

#define NN 4096
#define EE 16384
#define DD 13
#define RR 128
#define NP 4     // NUM_PARAMS (ORDER + 1)

// Transposed ho_params: [slot][type][d][r]  (source is [slot][type][r][d])
__device__ float g_hoT[3 * NP * DD * RR];

__global__ void k_transpose(const float* __restrict__ ho) {
    int idx = blockIdx.x * blockDim.x + threadIdx.x;
    const int total = 3 * NP * RR * DD;
    if (idx < total) {
        int d  = idx % DD;
        int r  = (idx / DD) % RR;
        int sp = idx / (DD * RR);
        g_hoT[(sp * DD + d) * RR + r] = ho[idx];
    }
}

__global__ void k_zero(float* __restrict__ out) {
    int i = blockIdx.x * blockDim.x + threadIdx.x;
    if (i < NN * DD) out[i] = 0.f;
}

// shared memory layout (floats)
#define S_BP   0                        // bp_params   [4][13][128]  = 6656
#define S_BPB  (NP * DD * RR)           // bp_bias     [4][128]      = 512
#define S_HO   (S_BPB + NP * RR)        // hoT         [3][4][13][128] = 19968
#define S_HOB  (S_HO + 3 * NP * DD * RR)// ho_bias     [3][4][13]    = 156
#define S_TOT  (S_HOB + 3 * NP * DD)    // 27292 floats = 109168 bytes

__global__ void __launch_bounds__(512, 1) k_main(
    const float* __restrict__ nodes,
    const float* __restrict__ bp_params,
    const float* __restrict__ bp_bias,
    const float* __restrict__ ho_bias,
    const int*   __restrict__ edges,
    const int*   __restrict__ edge_types,
    float*       __restrict__ out)
{
    extern __shared__ float sm[];
    for (int i = threadIdx.x; i < NP * DD * RR; i += blockDim.x)     sm[S_BP  + i] = bp_params[i];
    for (int i = threadIdx.x; i < NP * RR; i += blockDim.x)          sm[S_BPB + i] = bp_bias[i];
    for (int i = threadIdx.x; i < 3 * NP * DD * RR; i += blockDim.x) sm[S_HO  + i] = g_hoT[i];
    for (int i = threadIdx.x; i < 3 * NP * DD; i += blockDim.x)      sm[S_HOB + i] = ho_bias[i];
    __syncthreads();

    const int lane = threadIdx.x & 31;
    const int wid  = blockIdx.x * (blockDim.x >> 5) + (threadIdx.x >> 5);
    const int nw   = gridDim.x * (blockDim.x >> 5);

    for (int e = wid; e < EE; e += nw) {
        int nd[3], ty[3];
#pragma unroll
        for (int s = 0; s < 3; s++) {
            nd[s] = edges[e * 3 + s];
            ty[s] = edge_types[e * 3 + s];
        }

        // gather node rows (broadcast loads, L1/L2 hot)
        float rn[3][DD];
#pragma unroll
        for (int s = 0; s < 3; s++) {
            const float* p = nodes + nd[s] * DD;
#pragma unroll
            for (int d = 0; d < DD; d++) rn[s][d] = __ldg(p + d);
        }

        // ---- stage 1: t[s] = relu(rn[s] @ Wbp[type] + b), lane owns r = 4*lane..4*lane+3
        float4 t[3];
#pragma unroll
        for (int s = 0; s < 3; s++) {
            const float* wb = sm + S_BP + ty[s] * DD * RR;
            float4 acc = reinterpret_cast<const float4*>(sm + S_BPB + ty[s] * RR)[lane];
#pragma unroll
            for (int d = 0; d < DD; d++) {
                float4 w = reinterpret_cast<const float4*>(wb + d * RR)[lane];
                acc.x = fmaf(rn[s][d], w.x, acc.x);
                acc.y = fmaf(rn[s][d], w.y, acc.y);
                acc.z = fmaf(rn[s][d], w.z, acc.z);
                acc.w = fmaf(rn[s][d], w.w, acc.w);
            }
            t[s].x = fmaxf(acc.x, 0.f);
            t[s].y = fmaxf(acc.y, 0.f);
            t[s].z = fmaxf(acc.z, 0.f);
            t[s].w = fmaxf(acc.w, 0.f);
        }

        // ---- stage 2: per target slot, fact = prod of other slots, msg = fact @ Who
#pragma unroll
        for (int s = 0; s < 3; s++) {
            const int j = (s == 0) ? 1 : 0;
            const int k = (s == 2) ? 1 : 2;
            float4 f;
            f.x = t[j].x * t[k].x;
            f.y = t[j].y * t[k].y;
            f.z = t[j].z * t[k].z;
            f.w = t[j].w * t[k].w;

            const float* wh = sm + S_HO + (s * NP + ty[s]) * DD * RR;
            float ms[DD];
#pragma unroll
            for (int d = 0; d < DD; d++) {
                float4 w = reinterpret_cast<const float4*>(wh + d * RR)[lane];
                ms[d] = fmaf(f.w, w.w, fmaf(f.z, w.z, fmaf(f.y, w.y, f.x * w.x)));
            }
            // warp reduction of 13 partials to lane 0
#pragma unroll
            for (int d = 0; d < DD; d++) {
#pragma unroll
                for (int off = 16; off; off >>= 1)
                    ms[d] += __shfl_down_sync(0xffffffffu, ms[d], off);
            }
            if (lane == 0) {
                float* dst = out + nd[s] * DD;
                const float* hb = sm + S_HOB + (s * NP + ty[s]) * DD;
#pragma unroll
                for (int d = 0; d < DD; d++)
                    atomicAdd(dst + d, ms[d] + hb[d]);
            }
        }
    }
}

extern "C" void kernel_launch(void* const* d_in, const int* in_sizes, int n_in,
                              void* d_out, int out_size) {
    const float* nodes      = (const float*)d_in[0];
    const float* bp_params  = (const float*)d_in[1];
    const float* bp_bias    = (const float*)d_in[2];
    const float* ho_params  = (const float*)d_in[3];
    const float* ho_bias    = (const float*)d_in[4];
    const int*   edges      = (const int*)d_in[5];
    const int*   edge_types = (const int*)d_in[6];
    // d_in[7] = atoms, d_in[8] = atom_edges  (unused in BT mode)
    float* out = (float*)d_out;

    int sms = 0;
    cudaDeviceGetAttribute(&sms, cudaDevAttrMultiProcessorCount, 0);
    if (sms <= 0) sms = 148;
    cudaFuncSetAttribute(k_main, cudaFuncAttributeMaxDynamicSharedMemorySize, S_TOT * 4);

    k_transpose<<<(3 * NP * RR * DD + 255) / 256, 256>>>(ho_params);
    k_zero<<<(NN * DD + 255) / 256, 256>>>(out);
    k_main<<<sms, 512, S_TOT * 4>>>(nodes, bp_params, bp_bias, ho_bias,
                                    edges, edge_types, out);
}

// round 3
// speedup vs baseline: 1.0368x; 1.0368x over previous
#include <cuda_runtime.h>

#define NN 4096
#define EE 16384
#define DD 13
#define RR 128
#define NP 4          // NUM_PARAMS
#define HOSTRIDE 132  // padded smem row stride for transposed ho weights
#define PER 12        // edges per warp (multiple of 4)

__device__ int g_sorted[EE];

// shared memory layout (floats)
#define S_BP   0                               // bp_params [4][13][128]
#define S_BPB  (NP * DD * RR)                  // bp_bias   [4][128]
#define S_HO   (S_BPB + NP * RR)               // hoT       [3][4][13][132]
#define S_HOB  (S_HO + 3 * NP * DD * HOSTRIDE) // ho_bias   [3][4][13]
#define S_TOT  (S_HOB + 3 * NP * DD)           // 27928 floats ~ 111.7 KB

__global__ void k_zero(float* __restrict__ out) {
    int i = blockIdx.x * blockDim.x + threadIdx.x;
    if (i < NN * DD) out[i] = 0.f;
}

// Single-block bucket sort of edges by key = ty0*16+ty1*4+ty2 (64 buckets).
__global__ void k_prep(const int* __restrict__ et) {
    __shared__ int h[64], c[64];
    int tid = threadIdx.x;
    if (tid < 64) h[tid] = 0;
    __syncthreads();
    for (int e = tid; e < EE; e += blockDim.x) {
        int t0 = et[e * 3], t1 = et[e * 3 + 1], t2 = et[e * 3 + 2];
        atomicAdd(&h[t0 * 16 + t1 * 4 + t2], 1);
    }
    __syncthreads();
    if (tid == 0) {
        int run = 0;
        for (int k = 0; k < 64; k++) { c[k] = run; run += h[k]; }
    }
    __syncthreads();
    for (int e = tid; e < EE; e += blockDim.x) {
        int t0 = et[e * 3], t1 = et[e * 3 + 1], t2 = et[e * 3 + 2];
        int pos = atomicAdd(&c[t0 * 16 + t1 * 4 + t2], 1);
        g_sorted[pos] = e;
    }
}

// Redistribution-tree warp reduction of 13 per-lane values.
// After return, lane with (alive, sid) holds total of stream sid in return value.
// sid/alive are pure functions of lane id, precomputed by caller:
//   alive = !b0 && !(b1 && b2 && (b4|b3))
//   sid   = 7*b4 + (b4 ? 3*b3 : 4*b3) + 2*b2 + b1
__device__ __forceinline__ float tree13(float* v, int lane) {
    {   // xor 16: [0,13) -> low lanes keep [0,7), high lanes keep [7,13)
        float o[13];
#pragma unroll
        for (int i = 0; i < 13; i++) o[i] = __shfl_xor_sync(0xffffffffu, v[i], 16);
        if (lane & 16) {
#pragma unroll
            for (int i = 0; i < 6; i++) v[i] = v[i + 7] + o[i + 7];
        } else {
#pragma unroll
            for (int i = 0; i < 7; i++) v[i] = v[i] + o[i];
        }
    }
    {   // xor 8: 7 -> 4/3 (low), 6 -> 3/3 (high)
        float o[7];
#pragma unroll
        for (int i = 0; i < 7; i++) o[i] = __shfl_xor_sync(0xffffffffu, v[i], 8);
        if (!(lane & 16)) {
            if (lane & 8) { v[0] = v[4] + o[4]; v[1] = v[5] + o[5]; v[2] = v[6] + o[6]; }
            else { v[0] = v[0] + o[0]; v[1] = v[1] + o[1]; v[2] = v[2] + o[2]; v[3] = v[3] + o[3]; }
        } else {
            if (lane & 8) { v[0] = v[3] + o[3]; v[1] = v[4] + o[4]; v[2] = v[5] + o[5]; }
            else { v[0] = v[0] + o[0]; v[1] = v[1] + o[1]; v[2] = v[2] + o[2]; }
        }
    }
    {   // xor 4: 4 -> 2/2, 3 -> 2/1
        float o[4];
#pragma unroll
        for (int i = 0; i < 4; i++) o[i] = __shfl_xor_sync(0xffffffffu, v[i], 4);
        bool four = ((lane & 24) == 0);
        if (lane & 4) {
            v[0] = v[2] + o[2];
            if (four) v[1] = v[3] + o[3];
        } else {
            v[0] = v[0] + o[0];
            v[1] = v[1] + o[1];
        }
    }
    {   // xor 2: 2 -> 1/1 (cnt-1 groups: upper child dead)
        float o0 = __shfl_xor_sync(0xffffffffu, v[0], 2);
        float o1 = __shfl_xor_sync(0xffffffffu, v[1], 2);
        v[0] = (lane & 2) ? (v[1] + o1) : (v[0] + o0);
    }
    {   // xor 1
        float o0 = __shfl_xor_sync(0xffffffffu, v[0], 1);
        v[0] = v[0] + o0;  // odd lanes produce garbage; masked by alive
    }
    return v[0];
}

template <int B>
__device__ __forceinline__ void do_batch(
    const float* __restrict__ sm, const int* ids,
    int ty0, int ty1, int ty2,
    const float* __restrict__ nodes, const int* __restrict__ edges,
    float* __restrict__ out,
    int lane, int sid, bool alive)
{
    int nd[B][3];
#pragma unroll
    for (int b = 0; b < B; b++)
#pragma unroll
        for (int s = 0; s < 3; s++)
            nd[b][s] = __ldg(edges + ids[b] * 3 + s);

    // lane-parallel gather of 3 node rows (39 floats) per edge in 2 LDGs
    const int gs = lane / 13;
    const int gl = lane - gs * 13;
    float gv0[B], gv1[B];
#pragma unroll
    for (int b = 0; b < B; b++) {
        const float* p0 = nodes + nd[b][0] * DD;
        const float* p1 = nodes + nd[b][1] * DD;
        const float* p2 = nodes + nd[b][2] * DD;
        const float* ps = (gs == 0) ? p0 : ((gs == 1) ? p1 : p2);
        gv0[b] = __ldg(ps + gl);
        gv1[b] = (lane < 7) ? __ldg(p2 + 6 + lane) : 0.f;
    }

    const int ty[3] = {ty0, ty1, ty2};

    // ---- stage 1: t[s][b] = relu(rn @ Wbp[ty[s]] + bias); lane owns r=4*lane..+3
    float4 t[3][B];
#pragma unroll
    for (int s = 0; s < 3; s++) {
        const float* wb = sm + S_BP + ty[s] * DD * RR;
        float4 bias = reinterpret_cast<const float4*>(sm + S_BPB + ty[s] * RR)[lane];
#pragma unroll
        for (int b = 0; b < B; b++) t[s][b] = bias;
#pragma unroll
        for (int d = 0; d < DD; d++) {
            float4 w = reinterpret_cast<const float4*>(wb + d * RR)[lane];
            const int src = s * 13 + d;
#pragma unroll
            for (int b = 0; b < B; b++) {
                float rnv = (src < 32) ? __shfl_sync(0xffffffffu, gv0[b], src)
                                       : __shfl_sync(0xffffffffu, gv1[b], src - 32);
                t[s][b].x = fmaf(rnv, w.x, t[s][b].x);
                t[s][b].y = fmaf(rnv, w.y, t[s][b].y);
                t[s][b].z = fmaf(rnv, w.z, t[s][b].z);
                t[s][b].w = fmaf(rnv, w.w, t[s][b].w);
            }
        }
#pragma unroll
        for (int b = 0; b < B; b++) {
            t[s][b].x = fmaxf(t[s][b].x, 0.f);
            t[s][b].y = fmaxf(t[s][b].y, 0.f);
            t[s][b].z = fmaxf(t[s][b].z, 0.f);
            t[s][b].w = fmaxf(t[s][b].w, 0.f);
        }
    }

    // ---- stage 2: per target slot: fact = prod of other slots; msg = fact @ WhoT; scatter
#pragma unroll
    for (int s = 0; s < 3; s++) {
        const int j = (s == 0) ? 1 : 0;
        const int k = (s == 2) ? 1 : 2;
        const float* wh = sm + S_HO + (s * NP + ty[s]) * DD * HOSTRIDE;
        const float* hb = sm + S_HOB + (s * NP + ty[s]) * DD;
        // process edges in pairs to bound register pressure
#pragma unroll
        for (int p = 0; p < B; p += 2) {
            const int PB = (B - p >= 2) ? 2 : 1;
            float4 f[2];
#pragma unroll
            for (int q = 0; q < PB; q++) {
                f[q].x = t[j][p + q].x * t[k][p + q].x;
                f[q].y = t[j][p + q].y * t[k][p + q].y;
                f[q].z = t[j][p + q].z * t[k][p + q].z;
                f[q].w = t[j][p + q].w * t[k][p + q].w;
            }
            float ms[2][DD];
#pragma unroll
            for (int d = 0; d < DD; d++) {
                float4 w = reinterpret_cast<const float4*>(wh + d * HOSTRIDE)[lane];
#pragma unroll
                for (int q = 0; q < PB; q++) {
                    ms[q][d] = fmaf(f[q].w, w.w,
                               fmaf(f[q].z, w.z,
                               fmaf(f[q].y, w.y, f[q].x * w.x)));
                }
            }
#pragma unroll
            for (int q = 0; q < PB; q++) {
                float val = tree13(ms[q], lane);
                if (alive) {
                    float bias = hb[sid];
                    atomicAdd(out + nd[p + q][s] * DD + sid, val + bias);
                }
            }
        }
    }
}

__global__ void __launch_bounds__(384, 1) k_main(
    const float* __restrict__ nodes,
    const float* __restrict__ bp_params,
    const float* __restrict__ bp_bias,
    const float* __restrict__ ho_params,   // [3][NP][128][13] original layout
    const float* __restrict__ ho_bias,
    const int*   __restrict__ edges,
    const int*   __restrict__ et,
    float*       __restrict__ out)
{
    extern __shared__ float sm[];
    for (int i = threadIdx.x; i < NP * DD * RR; i += blockDim.x) sm[S_BP + i] = bp_params[i];
    for (int i = threadIdx.x; i < NP * RR; i += blockDim.x)      sm[S_BPB + i] = bp_bias[i];
    for (int i = threadIdx.x; i < 3 * NP * RR * DD; i += blockDim.x) {
        int d  = i % DD;
        int rd = i / DD;
        int r  = rd & (RR - 1);
        int sp = rd >> 7;
        sm[S_HO + (sp * DD + d) * HOSTRIDE + r] = ho_params[i];
    }
    for (int i = threadIdx.x; i < 3 * NP * DD; i += blockDim.x)  sm[S_HOB + i] = ho_bias[i];
    __syncthreads();

    const int lane = threadIdx.x & 31;
    const int wid  = blockIdx.x * (blockDim.x >> 5) + (threadIdx.x >> 5);
    const int e0 = wid * PER;
    if (e0 >= EE) return;
    int e1 = e0 + PER; if (e1 > EE) e1 = EE;

    // lane -> output stream mapping for the reduction tree
    const int b4 = (lane >> 4) & 1, b3 = (lane >> 3) & 1, b2 = (lane >> 2) & 1,
              b1 = (lane >> 1) & 1, b0 = lane & 1;
    const bool alive = (b0 == 0) && !(b1 && b2 && (b4 | b3));
    const int sid = 7 * b4 + (b4 ? 3 * b3 : 4 * b3) + 2 * b2 + b1;

    int e = e0;
    while (e < e1) {
        int ids[4];
        if (e + 4 <= e1) {
            int t0[4], t1[4], t2[4];
#pragma unroll
            for (int b = 0; b < 4; b++) ids[b] = g_sorted[e + b];
#pragma unroll
            for (int b = 0; b < 4; b++) {
                t0[b] = __ldg(et + ids[b] * 3 + 0);
                t1[b] = __ldg(et + ids[b] * 3 + 1);
                t2[b] = __ldg(et + ids[b] * 3 + 2);
            }
            bool uni = (t0[0] == t0[1] && t0[0] == t0[2] && t0[0] == t0[3] &&
                        t1[0] == t1[1] && t1[0] == t1[2] && t1[0] == t1[3] &&
                        t2[0] == t2[1] && t2[0] == t2[2] && t2[0] == t2[3]);
            if (uni) {
                do_batch<4>(sm, ids, t0[0], t1[0], t2[0], nodes, edges, out, lane, sid, alive);
                e += 4;
                continue;
            }
        }
        ids[0] = g_sorted[e];
        int a0 = __ldg(et + ids[0] * 3 + 0);
        int a1 = __ldg(et + ids[0] * 3 + 1);
        int a2 = __ldg(et + ids[0] * 3 + 2);
        do_batch<1>(sm, ids, a0, a1, a2, nodes, edges, out, lane, sid, alive);
        e += 1;
    }
}

extern "C" void kernel_launch(void* const* d_in, const int* in_sizes, int n_in,
                              void* d_out, int out_size) {
    const float* nodes      = (const float*)d_in[0];
    const float* bp_params  = (const float*)d_in[1];
    const float* bp_bias    = (const float*)d_in[2];
    const float* ho_params  = (const float*)d_in[3];
    const float* ho_bias    = (const float*)d_in[4];
    const int*   edges      = (const int*)d_in[5];
    const int*   edge_types = (const int*)d_in[6];
    float* out = (float*)d_out;

    int sms = 0;
    cudaDeviceGetAttribute(&sms, cudaDevAttrMultiProcessorCount, 0);
    if (sms <= 0) sms = 148;
    cudaFuncSetAttribute(k_main, cudaFuncAttributeMaxDynamicSharedMemorySize, S_TOT * 4);

    k_zero<<<(NN * DD + 255) / 256, 256>>>(out);
    k_prep<<<1, 1024>>>(edge_types);
    k_main<<<sms, 384, S_TOT * 4>>>(nodes, bp_params, bp_bias, ho_params, ho_bias,
                                    edges, edge_types, out);
}